// round 1
// baseline (speedup 1.0000x reference)
#include <cuda_runtime.h>
#include <cstdint>
#include <cstdio>

// Problem constants
#define B_    8
#define N_TOK 1024
#define M_TOK 1024
#define E_    768
#define L_    768
#define H_    12
#define HD_   64
#define LN_EPS 1e-5f

// ---------------- scratch (static __device__ — no allocations allowed) -----
__device__ float g_xn [B_ * N_TOK * E_];                    // LN1(x)
__device__ float g_yn [B_ * M_TOK * E_];                    // LN2(y)
__device__ float g_q  [B_ * N_TOK * L_];                    // q proj (reused as mlp mid)
__device__ float g_k  [B_ * M_TOK * L_];                    // k proj (reused as h_pre)
__device__ float g_kT [B_ * H_ * HD_ * M_TOK];              // k transposed [b,h,d,m]
__device__ float g_A  [(size_t)B_ * H_ * N_TOK * M_TOK];    // attention probs (403 MB)
__device__ float g_C  [(size_t)B_ * N_TOK * H_ * E_];       // A @ yn, layout [b,n,h,e'] (302 MB)
__device__ float g_wvT[H_ * E_ * E_];                       // Wv permuted to [h*E+e', e]
__device__ float g_bsum[E_];                                // sum_h bv_h
__device__ float g_hn [B_ * N_TOK * E_];                    // LN3 output

// ---------------- packed f32x2 helpers (FFMA2 path, sm_100+) ---------------
__device__ __forceinline__ unsigned long long pk2(float lo, float hi) {
    unsigned long long r;
    asm("mov.b64 %0, {%1,%2};" : "=l"(r) : "f"(lo), "f"(hi));
    return r;
}
__device__ __forceinline__ void upk2(unsigned long long v, float& lo, float& hi) {
    asm("mov.b64 {%0,%1}, %2;" : "=f"(lo), "=f"(hi) : "l"(v));
}
__device__ __forceinline__ void fma2(unsigned long long& d, unsigned long long a,
                                     unsigned long long b) {
    asm("fma.rn.f32x2 %0, %1, %2, %3;" : "=l"(d) : "l"(a), "l"(b), "l"(d));
}

// ---------------- LayerNorm: one block per row of 768 ----------------------
__global__ void ln_kernel(const float* __restrict__ in, const float* __restrict__ g,
                          const float* __restrict__ b, float* __restrict__ out) {
    __shared__ float red[256];
    int row = blockIdx.x;
    int t = threadIdx.x;
    const float* x = in + (size_t)row * E_;
    float* o = out + (size_t)row * E_;

    float v[3];
    float s = 0.f;
#pragma unroll
    for (int i = 0; i < 3; i++) { v[i] = x[t + i * 256]; s += v[i]; }
    red[t] = s; __syncthreads();
    for (int st = 128; st > 0; st >>= 1) { if (t < st) red[t] += red[t + st]; __syncthreads(); }
    float mean = red[0] * (1.0f / E_); __syncthreads();

    float sq = 0.f;
#pragma unroll
    for (int i = 0; i < 3; i++) { float d = v[i] - mean; sq += d * d; }
    red[t] = sq; __syncthreads();
    for (int st = 128; st > 0; st >>= 1) { if (t < st) red[t] += red[t + st]; __syncthreads(); }
    float rstd = rsqrtf(red[0] * (1.0f / E_) + LN_EPS);

#pragma unroll
    for (int i = 0; i < 3; i++) {
        int c = t + i * 256;
        o[c] = (v[i] - mean) * rstd * g[c] + b[c];
    }
}

// ---------------- softmax over rows of 1024 --------------------------------
__global__ void softmax_kernel(float* __restrict__ A) {
    __shared__ float red[256];
    size_t row = blockIdx.x;
    int t = threadIdx.x;
    float* p = A + row * (size_t)M_TOK;

    float v[4];
    float mx = -1e30f;
#pragma unroll
    for (int i = 0; i < 4; i++) { v[i] = p[t + i * 256]; mx = fmaxf(mx, v[i]); }
    red[t] = mx; __syncthreads();
    for (int st = 128; st > 0; st >>= 1) { if (t < st) red[t] = fmaxf(red[t], red[t + st]); __syncthreads(); }
    mx = red[0]; __syncthreads();

    float s = 0.f;
#pragma unroll
    for (int i = 0; i < 4; i++) { v[i] = expf(v[i] - mx); s += v[i]; }
    red[t] = s; __syncthreads();
    for (int st = 128; st > 0; st >>= 1) { if (t < st) red[t] += red[t + st]; __syncthreads(); }
    float inv = 1.0f / red[0];

#pragma unroll
    for (int i = 0; i < 4; i++) p[t + i * 256] = v[i] * inv;
}

// ---------------- prep: Wv permute + bias sum ------------------------------
__global__ void prep_wvT(const float* __restrict__ wv) {
    int idx = blockIdx.x * 256 + threadIdx.x;           // over H*E*E = 7077888
    if (idx >= H_ * E_ * E_) return;
    int e  = idx % E_;
    int tt = idx / E_;
    int ep = tt % E_;
    int h  = tt / E_;
    g_wvT[idx] = wv[(size_t)ep * (E_ * H_) + h * E_ + e];
}
__global__ void prep_bsum(const float* __restrict__ bv) {
    int e = blockIdx.x * 256 + threadIdx.x;
    if (e >= E_) return;
    float s = 0.f;
#pragma unroll
    for (int h = 0; h < H_; h++) s += bv[h * E_ + e];
    g_bsum[e] = s;
}

// ---------------- transpose k -> [b,h,d,m] ---------------------------------
__global__ void transpose_k() {
    int idx = blockIdx.x * 256 + threadIdx.x;           // over B*H*HD*M = 6291456
    if (idx >= B_ * H_ * HD_ * M_TOK) return;
    int m  = idx % M_TOK;
    int t2 = idx / M_TOK;
    int d  = t2 % HD_;
    int t3 = t2 / HD_;
    int h  = t3 % H_;
    int b  = t3 / H_;
    g_kT[idx] = g_k[((size_t)(b * M_TOK + m)) * L_ + h * HD_ + d];
}

// ---------------- copy -----------------------------------------------------
__global__ void copy_kernel(const float* __restrict__ src, float* __restrict__ dst, int n) {
    int i = blockIdx.x * 256 + threadIdx.x;
    if (i < n) dst[i] = src[i];
}

// ---------------- generic batched SGEMM (fp32, FFMA2 inner loop) -----------
// C[z] = alpha * A[z] @ B[z] (+ bias) (+ residual) (relu?)
// per-z offsets: off = (z/div)*s1 + (z%div)*s2  (div=1 -> plain z*s1)
#define BM 128
#define BN 128
#define BK 8
#define TM 8
#define TN 8

template <bool RELU>
__global__ __launch_bounds__(256) void sgemm(
    int M, int N, int K, int zdiv,
    const float* __restrict__ A, int lda, long long sA1, long long sA2,
    const float* __restrict__ B, int ldb, long long sB1, long long sB2,
    float* C, int ldc, long long sC1, long long sC2,
    const float* __restrict__ bias,
    const float* __restrict__ res, int ldr, long long sR1, long long sR2,
    float alpha)
{
    __shared__ __align__(16) float As[BK][BM];
    __shared__ __align__(16) float Bs[BK][BN];

    int z = blockIdx.z;
    long long zq = z / zdiv, zr = z % zdiv;
    A += zq * sA1 + zr * sA2;
    B += zq * sB1 + zr * sB2;
    C += zq * sC1 + zr * sC2;
    if (res) res += zq * sR1 + zr * sR2;

    int brow = blockIdx.y * BM, bcol = blockIdx.x * BN;
    int tid = threadIdx.x;
    int irA = tid >> 1, icA = (tid & 1) * 4;   // A tile: 128 rows x 8 k
    int irB = tid >> 5, icB = (tid & 31) * 4;  // B tile: 8 k x 128 cols
    int tx = tid & 15, ty = tid >> 4;

    unsigned long long acc[TM][TN / 2];
#pragma unroll
    for (int i = 0; i < TM; i++)
#pragma unroll
        for (int j = 0; j < TN / 2; j++) acc[i][j] = 0ULL;

    const float* Aptr = A + (size_t)brow * lda;
    const float* Bptr = B + bcol;

    for (int k0 = 0; k0 < K; k0 += BK) {
        float4 av = *reinterpret_cast<const float4*>(Aptr + (size_t)irA * lda + k0 + icA);
        As[icA + 0][irA] = av.x; As[icA + 1][irA] = av.y;
        As[icA + 2][irA] = av.z; As[icA + 3][irA] = av.w;
        float4 bv = *reinterpret_cast<const float4*>(Bptr + (size_t)(k0 + irB) * ldb + icB);
        *reinterpret_cast<float4*>(&Bs[irB][icB]) = bv;
        __syncthreads();

#pragma unroll
        for (int k = 0; k < BK; k++) {
            float4 a0 = *reinterpret_cast<const float4*>(&As[k][ty * TM]);
            float4 a1 = *reinterpret_cast<const float4*>(&As[k][ty * TM + 4]);
            float rm[TM] = {a0.x, a0.y, a0.z, a0.w, a1.x, a1.y, a1.z, a1.w};
            const unsigned long long* b2 =
                reinterpret_cast<const unsigned long long*>(&Bs[k][tx * TN]);
            unsigned long long rn[TN / 2];
#pragma unroll
            for (int j = 0; j < TN / 2; j++) rn[j] = b2[j];
#pragma unroll
            for (int i = 0; i < TM; i++) {
                unsigned long long a2 = pk2(rm[i], rm[i]);
#pragma unroll
                for (int j = 0; j < TN / 2; j++) fma2(acc[i][j], a2, rn[j]);
            }
        }
        __syncthreads();
    }

#pragma unroll
    for (int i = 0; i < TM; i++) {
        int row = brow + ty * TM + i;
        float outv[TN];
#pragma unroll
        for (int j = 0; j < TN / 2; j++) upk2(acc[i][j], outv[2 * j], outv[2 * j + 1]);
#pragma unroll
        for (int j = 0; j < TN; j++) {
            int col = bcol + tx * TN + j;
            float v = outv[j] * alpha;
            if (bias) v += bias[col];
            if (res)  v += res[(size_t)row * ldr + col];
            if (RELU) v = fmaxf(v, 0.f);
            outv[j] = v;
        }
        float4* cp = reinterpret_cast<float4*>(C + (size_t)row * ldc + bcol + tx * TN);
        cp[0] = make_float4(outv[0], outv[1], outv[2], outv[3]);
        cp[1] = make_float4(outv[4], outv[5], outv[6], outv[7]);
    }
}

// ---------------- launch ---------------------------------------------------
extern "C" void kernel_launch(void* const* d_in, const int* in_sizes, int n_in,
                              void* d_out, int out_size) {
    const float* x     = (const float*)d_in[0];
    const float* y     = (const float*)d_in[1];
    const float* ln1_g = (const float*)d_in[2];
    const float* ln1_b = (const float*)d_in[3];
    const float* ln2_g = (const float*)d_in[4];
    const float* ln2_b = (const float*)d_in[5];
    const float* ln3_g = (const float*)d_in[6];
    const float* ln3_b = (const float*)d_in[7];
    const float* wq    = (const float*)d_in[8];
    const float* bq    = (const float*)d_in[9];
    const float* wk    = (const float*)d_in[10];
    const float* bk    = (const float*)d_in[11];
    const float* wv    = (const float*)d_in[12];
    const float* bv    = (const float*)d_in[13];
    const float* w_in  = (const float*)d_in[14];
    const float* b_in  = (const float*)d_in[15];
    const float* w_out = (const float*)d_in[16];
    const float* b_out = (const float*)d_in[17];
    float* out = (float*)d_out;

    float *p_xn, *p_yn, *p_q, *p_k, *p_kT, *p_A, *p_C, *p_wvT, *p_bsum, *p_hn;
    cudaGetSymbolAddress((void**)&p_xn,   g_xn);
    cudaGetSymbolAddress((void**)&p_yn,   g_yn);
    cudaGetSymbolAddress((void**)&p_q,    g_q);
    cudaGetSymbolAddress((void**)&p_k,    g_k);
    cudaGetSymbolAddress((void**)&p_kT,   g_kT);
    cudaGetSymbolAddress((void**)&p_A,    g_A);
    cudaGetSymbolAddress((void**)&p_C,    g_C);
    cudaGetSymbolAddress((void**)&p_wvT,  g_wvT);
    cudaGetSymbolAddress((void**)&p_bsum, g_bsum);
    cudaGetSymbolAddress((void**)&p_hn,   g_hn);
    float* p_hpre = p_k;   // reuse after transpose_k consumed g_k
    float* p_mid  = p_q;   // reuse after scores consumed g_q

    const int ROWS = B_ * N_TOK;               // 8192 token rows
    const size_t CH = (size_t)B_ * N_TOK * E_; // 6291456 elems per output tensor

    // 1. LayerNorms
    ln_kernel<<<ROWS, 256>>>(x, ln1_g, ln1_b, p_xn);
    ln_kernel<<<B_ * M_TOK, 256>>>(y, ln2_g, ln2_b, p_yn);

    // 2. prep Wv permutation + bias sum
    prep_wvT<<<(H_ * E_ * E_ + 255) / 256, 256>>>(wv);
    prep_bsum<<<(E_ + 255) / 256, 256>>>(bv);

    // 3. q / k projections: [8192,768] = [8192,768] @ [768,768] + bias
    sgemm<false><<<dim3(E_ / BN, ROWS / BM, 1), 256>>>(
        ROWS, L_, E_, 1,
        p_xn, E_, 0, 0,  wq, L_, 0, 0,  p_q, L_, 0, 0,
        bq, nullptr, 0, 0, 0, 1.0f);
    sgemm<false><<<dim3(E_ / BN, ROWS / BM, 1), 256>>>(
        ROWS, L_, E_, 1,
        p_yn, E_, 0, 0,  wk, L_, 0, 0,  p_k, L_, 0, 0,
        bk, nullptr, 0, 0, 0, 1.0f);

    // 4. transpose k to [b,h,d,m]
    transpose_k<<<(B_ * H_ * HD_ * M_TOK + 255) / 256, 256>>>();

    // 5. scores: per (b,h): [1024,1024] = q_h[1024,64] @ kT_h[64,1024], alpha=1/8
    sgemm<false><<<dim3(M_TOK / BN, N_TOK / BM, B_ * H_), 256>>>(
        N_TOK, M_TOK, HD_, H_,
        p_q, L_, (long long)N_TOK * L_, HD_,
        p_kT, M_TOK, (long long)H_ * HD_ * M_TOK, (long long)HD_ * M_TOK,
        p_A, M_TOK, (long long)H_ * N_TOK * M_TOK, (long long)N_TOK * M_TOK,
        nullptr, nullptr, 0, 0, 0, 0.125f);

    // 6. softmax over m
    softmax_kernel<<<B_ * H_ * N_TOK, 256>>>(p_A);

    // 7. C = A_h @ yn : per (b,h) [1024,768], stored [b,n,h,e']
    sgemm<false><<<dim3(E_ / BN, N_TOK / BM, B_ * H_), 256>>>(
        N_TOK, E_, M_TOK, H_,
        p_A, M_TOK, (long long)H_ * N_TOK * M_TOK, (long long)N_TOK * M_TOK,
        p_yn, E_, (long long)M_TOK * E_, 0,
        p_C, H_ * E_, (long long)N_TOK * H_ * E_, E_,
        nullptr, nullptr, 0, 0, 0, 1.0f);

    // 8. h_pre = xn + C @ WvT + sum_h bv_h : [8192,768], K=9216
    sgemm<false><<<dim3(E_ / BN, ROWS / BM, 1), 256>>>(
        ROWS, E_, H_ * E_, 1,
        p_C, H_ * E_, 0, 0,  p_wvT, E_, 0, 0,  p_hpre, E_, 0, 0,
        p_bsum, p_xn, E_, 0, 0, 1.0f);

    // 9. LN3
    ln_kernel<<<ROWS, 256>>>(p_hpre, ln3_g, ln3_b, p_hn);

    // 10. mid = relu(hn @ w_in + b_in)
    sgemm<true><<<dim3(L_ / BN, ROWS / BM, 1), 256>>>(
        ROWS, L_, E_, 1,
        p_hn, E_, 0, 0,  w_in, L_, 0, 0,  p_mid, L_, 0, 0,
        b_in, nullptr, 0, 0, 0, 1.0f);

    // 11. out = hn + mid @ w_out + b_out  -> d_out[0:CH]
    sgemm<false><<<dim3(E_ / BN, ROWS / BM, 1), 256>>>(
        ROWS, E_, L_, 1,
        p_mid, L_, 0, 0,  w_out, E_, 0, 0,  out, E_, 0, 0,
        b_out, p_hn, E_, 0, 0, 1.0f);

    // 12. second output: yn
    if ((size_t)out_size >= 2 * CH)
        copy_kernel<<<(int)((CH + 255) / 256), 256>>>(p_yn, out + CH, (int)CH);
}

// round 3
// speedup vs baseline: 2.9894x; 2.9894x over previous
#include <cuda_runtime.h>
#include <cstdint>
#include <cstdio>

// Problem constants
#define B_    8
#define N_TOK 1024
#define M_TOK 1024
#define E_    768
#define L_    768
#define H_    12
#define HD_   64
#define LN_EPS 1e-5f

// ---------------- scratch (static __device__ — no allocations allowed) -----
__device__ float g_xn  [B_ * N_TOK * E_];
__device__ float g_yn  [B_ * M_TOK * E_];
__device__ float g_ynT [B_ * E_ * M_TOK];                 // yn transposed per batch
__device__ float g_q   [B_ * N_TOK * L_];                 // q proj (reused as mlp mid)
__device__ float g_k   [B_ * M_TOK * L_];                 // k proj (reused as h_pre)
__device__ float g_A   [(size_t)B_ * H_ * N_TOK * M_TOK]; // attention probs (403 MB)
__device__ float g_C   [(size_t)B_ * N_TOK * H_ * E_];    // A @ yn, layout [b,n,h,e']
__device__ float g_w2T [E_ * H_ * E_];                    // [e, h*E+e'] = wv[e', h*E+e]
__device__ float g_wqT [L_ * E_];
__device__ float g_wkT [L_ * E_];
__device__ float g_winT[L_ * E_];
__device__ float g_woutT[E_ * L_];
__device__ float g_bsum[E_];
__device__ float g_hn  [B_ * N_TOK * E_];

// ---------------- tf32 helpers ---------------------------------------------
__device__ __forceinline__ float tf32f(float f) {
    uint32_t u; asm("cvt.rna.tf32.f32 %0, %1;" : "=r"(u) : "f"(f));
    return __uint_as_float(u);
}
__device__ __forceinline__ void mma_tf32(float& c0, float& c1, float& c2, float& c3,
                                         uint32_t a0, uint32_t a1, uint32_t a2, uint32_t a3,
                                         uint32_t b0, uint32_t b1) {
    asm volatile(
        "mma.sync.aligned.m16n8k8.row.col.f32.tf32.tf32.f32 "
        "{%0,%1,%2,%3}, {%4,%5,%6,%7}, {%8,%9}, {%0,%1,%2,%3};"
        : "+f"(c0), "+f"(c1), "+f"(c2), "+f"(c3)
        : "r"(a0), "r"(a1), "r"(a2), "r"(a3), "r"(b0), "r"(b1));
}

// ---------------- LayerNorm ------------------------------------------------
__global__ void ln_kernel(const float* __restrict__ in, const float* __restrict__ g,
                          const float* __restrict__ b, float* __restrict__ out) {
    __shared__ float red[256];
    int row = blockIdx.x;
    int t = threadIdx.x;
    const float* x = in + (size_t)row * E_;
    float* o = out + (size_t)row * E_;

    float v[3];
    float s = 0.f;
#pragma unroll
    for (int i = 0; i < 3; i++) { v[i] = x[t + i * 256]; s += v[i]; }
    red[t] = s; __syncthreads();
    for (int st = 128; st > 0; st >>= 1) { if (t < st) red[t] += red[t + st]; __syncthreads(); }
    float mean = red[0] * (1.0f / E_); __syncthreads();

    float sq = 0.f;
#pragma unroll
    for (int i = 0; i < 3; i++) { float d = v[i] - mean; sq += d * d; }
    red[t] = sq; __syncthreads();
    for (int st = 128; st > 0; st >>= 1) { if (t < st) red[t] += red[t + st]; __syncthreads(); }
    float rstd = rsqrtf(red[0] * (1.0f / E_) + LN_EPS);

#pragma unroll
    for (int i = 0; i < 3; i++) {
        int c = t + i * 256;
        o[c] = (v[i] - mean) * rstd * g[c] + b[c];
    }
}

// ---------------- softmax over rows of 1024 --------------------------------
__global__ void softmax_kernel(float* __restrict__ A) {
    __shared__ float red[256];
    size_t row = blockIdx.x;
    int t = threadIdx.x;
    float* p = A + row * (size_t)M_TOK;

    float v[4];
    float mx = -1e30f;
#pragma unroll
    for (int i = 0; i < 4; i++) { v[i] = p[t + i * 256]; mx = fmaxf(mx, v[i]); }
    red[t] = mx; __syncthreads();
    for (int st = 128; st > 0; st >>= 1) { if (t < st) red[t] = fmaxf(red[t], red[t + st]); __syncthreads(); }
    mx = red[0]; __syncthreads();

    float s = 0.f;
#pragma unroll
    for (int i = 0; i < 4; i++) { v[i] = expf(v[i] - mx); s += v[i]; }
    red[t] = s; __syncthreads();
    for (int st = 128; st > 0; st >>= 1) { if (t < st) red[t] += red[t + st]; __syncthreads(); }
    float inv = 1.0f / red[0];

#pragma unroll
    for (int i = 0; i < 4; i++) p[t + i * 256] = v[i] * inv;
}

// ---------------- generic strided transpose: out[c][r] = in[r][c] ----------
__global__ void transpose2(const float* __restrict__ in, int ldin, long long zin,
                           float* __restrict__ out, int ldout, long long zout) {
    __shared__ float t[32][33];
    in  += (long long)blockIdx.z * zin;
    out += (long long)blockIdx.z * zout;
    int r0 = blockIdx.y * 32, c0 = blockIdx.x * 32;
    int x = threadIdx.x, y = threadIdx.y;
#pragma unroll
    for (int i = 0; i < 32; i += 8) t[y + i][x] = in[(size_t)(r0 + y + i) * ldin + c0 + x];
    __syncthreads();
#pragma unroll
    for (int i = 0; i < 32; i += 8) out[(size_t)(c0 + y + i) * ldout + r0 + x] = t[x][y + i];
}

__global__ void prep_bsum(const float* __restrict__ bv) {
    int e = blockIdx.x * 256 + threadIdx.x;
    if (e >= E_) return;
    float s = 0.f;
#pragma unroll
    for (int h = 0; h < H_; h++) s += bv[h * E_ + e];
    g_bsum[e] = s;
}

__global__ void copy_kernel(const float* __restrict__ src, float* __restrict__ dst, int n) {
    int i = blockIdx.x * 256 + threadIdx.x;
    if (i < n) dst[i] = src[i];
}

// ---------------- mma.sync tf32 GEMM, 128x128 tile, BK=16 ------------------
// D = alpha * Aop @ Bop^T  (Aop: [M,K] K-major, Bop: [N,K] K-major)
// 8 warps: 4 (m) x 2 (n); warp tile 32x64 = 2 x 8 fragments of m16n8.
// Smem layout [k][row] with row-stride 136 floats -> conflict-free frag LDS.
#define SSTR 136

template <bool RELU>
__global__ __launch_bounds__(256) void tgemm(
    int K, int zdiv,
    const float* __restrict__ A, int lda, long long sA1, long long sA2,
    const float* __restrict__ Bop, int ldb, long long sB1, long long sB2,
    float* C, int ldc, long long sC1, long long sC2,
    const float* __restrict__ bias,
    const float* __restrict__ res, int ldr, long long sR1, long long sR2,
    float alpha)
{
    __shared__ float As[2][16][SSTR];
    __shared__ float Bs[2][16][SSTR];

    int tid = threadIdx.x;
    int wid = tid >> 5;
    int lane = tid & 31;
    int g = lane >> 2;        // groupID 0..7
    int tig = lane & 3;       // thread-in-group 0..3
    int warp_m = wid & 3;     // 0..3 -> 32-row slab
    int warp_n = wid >> 2;    // 0..1 -> 64-col slab

    int z = blockIdx.z;
    long long zq = z / zdiv, zr = z % zdiv;
    A   += zq * sA1 + zr * sA2;
    Bop += zq * sB1 + zr * sB2;
    C   += zq * sC1 + zr * sC2;
    if (res) res += zq * sR1 + zr * sR2;

    int brow = blockIdx.y * 128;
    int bcol = blockIdx.x * 128;

    // staging coords: each thread loads 16 consecutive k of one row (2x float4)
    int sr = tid >> 1;            // 0..127
    int sk = (tid & 1) * 8;       // 0 or 8

    const float* Ag = A + (size_t)(brow + sr) * lda + sk;
    const float* Bg = Bop + (size_t)(bcol + sr) * ldb + sk;

    float acc[2][8][4];
#pragma unroll
    for (int i = 0; i < 2; i++)
#pragma unroll
        for (int j = 0; j < 8; j++)
#pragma unroll
            for (int c = 0; c < 4; c++) acc[i][j][c] = 0.f;

    int nchunk = K >> 4;

    // prologue: stage chunk 0
    {
        float4 a0 = *reinterpret_cast<const float4*>(Ag);
        float4 a1 = *reinterpret_cast<const float4*>(Ag + 4);
        float4 b0 = *reinterpret_cast<const float4*>(Bg);
        float4 b1 = *reinterpret_cast<const float4*>(Bg + 4);
        As[0][sk + 0][sr] = tf32f(a0.x); As[0][sk + 1][sr] = tf32f(a0.y);
        As[0][sk + 2][sr] = tf32f(a0.z); As[0][sk + 3][sr] = tf32f(a0.w);
        As[0][sk + 4][sr] = tf32f(a1.x); As[0][sk + 5][sr] = tf32f(a1.y);
        As[0][sk + 6][sr] = tf32f(a1.z); As[0][sk + 7][sr] = tf32f(a1.w);
        Bs[0][sk + 0][sr] = tf32f(b0.x); Bs[0][sk + 1][sr] = tf32f(b0.y);
        Bs[0][sk + 2][sr] = tf32f(b0.z); Bs[0][sk + 3][sr] = tf32f(b0.w);
        Bs[0][sk + 4][sr] = tf32f(b1.x); Bs[0][sk + 5][sr] = tf32f(b1.y);
        Bs[0][sk + 6][sr] = tf32f(b1.z); Bs[0][sk + 7][sr] = tf32f(b1.w);
    }
    __syncthreads();

    int arow0 = warp_m * 32 + g;       // fragment row (mi adds 16)
    int bcol0 = warp_n * 64 + g;       // fragment col (nj adds 8)

    for (int i = 0; i < nchunk; i++) {
        int buf = i & 1;
        float4 pa0, pa1, pb0, pb1;
        if (i + 1 < nchunk) {
            const float* Ap = Ag + (size_t)(i + 1) * 16;
            const float* Bp = Bg + (size_t)(i + 1) * 16;
            pa0 = *reinterpret_cast<const float4*>(Ap);
            pa1 = *reinterpret_cast<const float4*>(Ap + 4);
            pb0 = *reinterpret_cast<const float4*>(Bp);
            pb1 = *reinterpret_cast<const float4*>(Bp + 4);
        }

#pragma unroll
        for (int ks = 0; ks < 2; ks++) {
            int kb = ks * 8 + tig;
            uint32_t a[2][4];
#pragma unroll
            for (int mi = 0; mi < 2; mi++) {
                int r0 = arow0 + mi * 16;
                a[mi][0] = __float_as_uint(As[buf][kb][r0]);
                a[mi][1] = __float_as_uint(As[buf][kb][r0 + 8]);
                a[mi][2] = __float_as_uint(As[buf][kb + 4][r0]);
                a[mi][3] = __float_as_uint(As[buf][kb + 4][r0 + 8]);
            }
#pragma unroll
            for (int nj = 0; nj < 8; nj++) {
                int c0 = bcol0 + nj * 8;
                uint32_t b0 = __float_as_uint(Bs[buf][kb][c0]);
                uint32_t b1 = __float_as_uint(Bs[buf][kb + 4][c0]);
#pragma unroll
                for (int mi = 0; mi < 2; mi++)
                    mma_tf32(acc[mi][nj][0], acc[mi][nj][1], acc[mi][nj][2], acc[mi][nj][3],
                             a[mi][0], a[mi][1], a[mi][2], a[mi][3], b0, b1);
            }
        }

        if (i + 1 < nchunk) {
            int nb = (i + 1) & 1;
            As[nb][sk + 0][sr] = tf32f(pa0.x); As[nb][sk + 1][sr] = tf32f(pa0.y);
            As[nb][sk + 2][sr] = tf32f(pa0.z); As[nb][sk + 3][sr] = tf32f(pa0.w);
            As[nb][sk + 4][sr] = tf32f(pa1.x); As[nb][sk + 5][sr] = tf32f(pa1.y);
            As[nb][sk + 6][sr] = tf32f(pa1.z); As[nb][sk + 7][sr] = tf32f(pa1.w);
            Bs[nb][sk + 0][sr] = tf32f(pb0.x); Bs[nb][sk + 1][sr] = tf32f(pb0.y);
            Bs[nb][sk + 2][sr] = tf32f(pb0.z); Bs[nb][sk + 3][sr] = tf32f(pb0.w);
            Bs[nb][sk + 4][sr] = tf32f(pb1.x); Bs[nb][sk + 5][sr] = tf32f(pb1.y);
            Bs[nb][sk + 6][sr] = tf32f(pb1.z); Bs[nb][sk + 7][sr] = tf32f(pb1.w);
        }
        __syncthreads();
    }

    // epilogue
#pragma unroll
    for (int mi = 0; mi < 2; mi++) {
        int r0 = brow + warp_m * 32 + mi * 16 + g;
#pragma unroll
        for (int nj = 0; nj < 8; nj++) {
            int col = bcol + warp_n * 64 + nj * 8 + 2 * tig;
            float2 bl = bias ? *reinterpret_cast<const float2*>(bias + col)
                             : make_float2(0.f, 0.f);
            float v0 = acc[mi][nj][0] * alpha + bl.x;
            float v1 = acc[mi][nj][1] * alpha + bl.y;
            float v2 = acc[mi][nj][2] * alpha + bl.x;
            float v3 = acc[mi][nj][3] * alpha + bl.y;
            if (res) {
                float2 r0v = *reinterpret_cast<const float2*>(res + (size_t)r0 * ldr + col);
                float2 r1v = *reinterpret_cast<const float2*>(res + (size_t)(r0 + 8) * ldr + col);
                v0 += r0v.x; v1 += r0v.y; v2 += r1v.x; v3 += r1v.y;
            }
            if (RELU) {
                v0 = fmaxf(v0, 0.f); v1 = fmaxf(v1, 0.f);
                v2 = fmaxf(v2, 0.f); v3 = fmaxf(v3, 0.f);
            }
            *reinterpret_cast<float2*>(C + (size_t)r0 * ldc + col) = make_float2(v0, v1);
            *reinterpret_cast<float2*>(C + (size_t)(r0 + 8) * ldc + col) = make_float2(v2, v3);
        }
    }
}

// ---------------- launch ---------------------------------------------------
extern "C" void kernel_launch(void* const* d_in, const int* in_sizes, int n_in,
                              void* d_out, int out_size) {
    const float* x     = (const float*)d_in[0];
    const float* y     = (const float*)d_in[1];
    const float* ln1_g = (const float*)d_in[2];
    const float* ln1_b = (const float*)d_in[3];
    const float* ln2_g = (const float*)d_in[4];
    const float* ln2_b = (const float*)d_in[5];
    const float* ln3_g = (const float*)d_in[6];
    const float* ln3_b = (const float*)d_in[7];
    const float* wq    = (const float*)d_in[8];
    const float* bq    = (const float*)d_in[9];
    const float* wk    = (const float*)d_in[10];
    const float* bk    = (const float*)d_in[11];
    const float* wv    = (const float*)d_in[12];
    const float* bv    = (const float*)d_in[13];
    const float* w_in  = (const float*)d_in[14];
    const float* b_in  = (const float*)d_in[15];
    const float* w_out = (const float*)d_in[16];
    const float* b_out = (const float*)d_in[17];
    float* out = (float*)d_out;

    float *p_xn, *p_yn, *p_ynT, *p_q, *p_k, *p_A, *p_C, *p_w2T;
    float *p_wqT, *p_wkT, *p_winT, *p_woutT, *p_bsum, *p_hn;
    cudaGetSymbolAddress((void**)&p_xn,    g_xn);
    cudaGetSymbolAddress((void**)&p_yn,    g_yn);
    cudaGetSymbolAddress((void**)&p_ynT,   g_ynT);
    cudaGetSymbolAddress((void**)&p_q,     g_q);
    cudaGetSymbolAddress((void**)&p_k,     g_k);
    cudaGetSymbolAddress((void**)&p_A,     g_A);
    cudaGetSymbolAddress((void**)&p_C,     g_C);
    cudaGetSymbolAddress((void**)&p_w2T,   g_w2T);
    cudaGetSymbolAddress((void**)&p_wqT,   g_wqT);
    cudaGetSymbolAddress((void**)&p_wkT,   g_wkT);
    cudaGetSymbolAddress((void**)&p_winT,  g_winT);
    cudaGetSymbolAddress((void**)&p_woutT, g_woutT);
    cudaGetSymbolAddress((void**)&p_bsum,  g_bsum);
    cudaGetSymbolAddress((void**)&p_hn,    g_hn);
    float* p_hpre = p_k;   // reuse after scores GEMM consumed g_k
    float* p_mid  = p_q;   // reuse after scores GEMM consumed g_q

    const int ROWS = B_ * N_TOK;               // 8192
    const size_t CH = (size_t)B_ * N_TOK * E_; // 6291456

    dim3 tb(32, 8);

    // 1. LayerNorms
    ln_kernel<<<ROWS, 256>>>(x, ln1_g, ln1_b, p_xn);
    ln_kernel<<<B_ * M_TOK, 256>>>(y, ln2_g, ln2_b, p_yn);

    // 2. transposes + bias sum
    transpose2<<<dim3(24, 24, 1), tb>>>(wq,    L_,   0, p_wqT,   E_,   0);
    transpose2<<<dim3(24, 24, 1), tb>>>(wk,    L_,   0, p_wkT,   E_,   0);
    transpose2<<<dim3(24, 24, 1), tb>>>(w_in,  L_,   0, p_winT,  E_,   0);
    transpose2<<<dim3(24, 24, 1), tb>>>(w_out, E_,   0, p_woutT, L_,   0);
    transpose2<<<dim3(24, 24, H_), tb>>>(wv, H_ * E_, E_, p_w2T, H_ * E_, E_);
    transpose2<<<dim3(24, 32, B_), tb>>>(p_yn, E_, (long long)M_TOK * E_,
                                          p_ynT, M_TOK, (long long)E_ * M_TOK);
    prep_bsum<<<3, 256>>>(bv);

    // 3. q / k projections
    tgemm<false><<<dim3(6, 64, 1), 256>>>(
        E_, 1, p_xn, E_, 0, 0, p_wqT, E_, 0, 0, p_q, L_, 0, 0,
        bq, nullptr, 0, 0, 0, 1.0f);
    tgemm<false><<<dim3(6, 64, 1), 256>>>(
        E_, 1, p_yn, E_, 0, 0, p_wkT, E_, 0, 0, p_k, L_, 0, 0,
        bk, nullptr, 0, 0, 0, 1.0f);

    // 4. scores: per (b,h) D[1024,1024] = q_h @ k_h^T, alpha = 1/8
    tgemm<false><<<dim3(8, 8, B_ * H_), 256>>>(
        HD_, H_,
        p_q, L_, (long long)N_TOK * L_, HD_,
        p_k, L_, (long long)M_TOK * L_, HD_,
        p_A, M_TOK, (long long)H_ * N_TOK * M_TOK, (long long)N_TOK * M_TOK,
        nullptr, nullptr, 0, 0, 0, 0.125f);

    // 5. softmax
    softmax_kernel<<<B_ * H_ * N_TOK, 256>>>(p_A);

    // 6. C = A_h @ yn  (B operand = ynT[b])
    tgemm<false><<<dim3(6, 8, B_ * H_), 256>>>(
        M_TOK, H_,
        p_A, M_TOK, (long long)H_ * N_TOK * M_TOK, (long long)N_TOK * M_TOK,
        p_ynT, M_TOK, (long long)E_ * M_TOK, 0,
        p_C, H_ * E_, (long long)N_TOK * H_ * E_, E_,
        nullptr, nullptr, 0, 0, 0, 1.0f);

    // 7. h_pre = xn + C @ W2 + bsum
    tgemm<false><<<dim3(6, 64, 1), 256>>>(
        H_ * E_, 1,
        p_C, H_ * E_, 0, 0, p_w2T, H_ * E_, 0, 0, p_hpre, E_, 0, 0,
        p_bsum, p_xn, E_, 0, 0, 1.0f);

    // 8. LN3
    ln_kernel<<<ROWS, 256>>>(p_hpre, ln3_g, ln3_b, p_hn);

    // 9. mid = relu(hn @ w_in + b_in)
    tgemm<true><<<dim3(6, 64, 1), 256>>>(
        E_, 1, p_hn, E_, 0, 0, p_winT, E_, 0, 0, p_mid, L_, 0, 0,
        b_in, nullptr, 0, 0, 0, 1.0f);

    // 10. out = hn + mid @ w_out + b_out
    tgemm<false><<<dim3(6, 64, 1), 256>>>(
        L_, 1, p_mid, L_, 0, 0, p_woutT, L_, 0, 0, out, E_, 0, 0,
        b_out, p_hn, E_, 0, 0, 1.0f);

    // 11. second output: yn
    if ((size_t)out_size >= 2 * CH)
        copy_kernel<<<(int)((CH + 255) / 256), 256>>>(p_yn, out + CH, (int)CH);
}

// round 4
// speedup vs baseline: 4.0383x; 1.3509x over previous
#include <cuda_runtime.h>
#include <cstdint>
#include <cstdio>

// Problem constants
#define B_    8
#define N_TOK 1024
#define M_TOK 1024
#define E_    768
#define L_    768
#define H_    12
#define HD_   64
#define LN_EPS 1e-5f

// ---------------- scratch (static __device__ — no allocations allowed) -----
__device__ float g_xn  [B_ * N_TOK * E_];
__device__ float g_yn  [B_ * M_TOK * E_];
__device__ float g_ynT [B_ * E_ * M_TOK];                 // yn transposed per batch
__device__ float g_q   [B_ * N_TOK * L_];                 // q proj (reused as mlp mid)
__device__ float g_k   [B_ * M_TOK * L_];                 // k proj (reused as h_pre)
__device__ float g_A   [(size_t)B_ * H_ * N_TOK * M_TOK]; // attention probs
__device__ float g_C   [(size_t)B_ * N_TOK * H_ * E_];    // A @ yn, layout [b,n,h,e']
__device__ float g_w2T [E_ * H_ * E_];                    // [e, h*E+e'] = wv[e', h*E+e]
__device__ float g_wqT [L_ * E_];
__device__ float g_wkT [L_ * E_];
__device__ float g_winT[L_ * E_];
__device__ float g_woutT[E_ * L_];
__device__ float g_bsum[E_];
__device__ float g_hn  [B_ * N_TOK * E_];

// ---------------- bf16 helpers ---------------------------------------------
__device__ __forceinline__ uint32_t bf2(float lo, float hi) {
    uint32_t r;
    asm("cvt.rn.bf16x2.f32 %0, %1, %2;" : "=r"(r) : "f"(hi), "f"(lo));
    return r;
}
__device__ __forceinline__ void mma_bf16(float& c0, float& c1, float& c2, float& c3,
                                         uint32_t a0, uint32_t a1, uint32_t a2, uint32_t a3,
                                         uint32_t b0, uint32_t b1) {
    asm volatile(
        "mma.sync.aligned.m16n8k16.row.col.f32.bf16.bf16.f32 "
        "{%0,%1,%2,%3}, {%4,%5,%6,%7}, {%8,%9}, {%0,%1,%2,%3};"
        : "+f"(c0), "+f"(c1), "+f"(c2), "+f"(c3)
        : "r"(a0), "r"(a1), "r"(a2), "r"(a3), "r"(b0), "r"(b1));
}

// ---------------- LayerNorm ------------------------------------------------
__global__ void ln_kernel(const float* __restrict__ in, const float* __restrict__ g,
                          const float* __restrict__ b, float* __restrict__ out) {
    __shared__ float red[256];
    int row = blockIdx.x;
    int t = threadIdx.x;
    const float* x = in + (size_t)row * E_;
    float* o = out + (size_t)row * E_;

    float v[3];
    float s = 0.f;
#pragma unroll
    for (int i = 0; i < 3; i++) { v[i] = x[t + i * 256]; s += v[i]; }
    red[t] = s; __syncthreads();
    for (int st = 128; st > 0; st >>= 1) { if (t < st) red[t] += red[t + st]; __syncthreads(); }
    float mean = red[0] * (1.0f / E_); __syncthreads();

    float sq = 0.f;
#pragma unroll
    for (int i = 0; i < 3; i++) { float d = v[i] - mean; sq += d * d; }
    red[t] = sq; __syncthreads();
    for (int st = 128; st > 0; st >>= 1) { if (t < st) red[t] += red[t + st]; __syncthreads(); }
    float rstd = rsqrtf(red[0] * (1.0f / E_) + LN_EPS);

#pragma unroll
    for (int i = 0; i < 3; i++) {
        int c = t + i * 256;
        o[c] = (v[i] - mean) * rstd * g[c] + b[c];
    }
}

// ---------------- softmax over rows of 1024 --------------------------------
__global__ void softmax_kernel(float* __restrict__ A) {
    __shared__ float red[256];
    size_t row = blockIdx.x;
    int t = threadIdx.x;
    float* p = A + row * (size_t)M_TOK;

    float v[4];
    float mx = -1e30f;
#pragma unroll
    for (int i = 0; i < 4; i++) { v[i] = p[t + i * 256]; mx = fmaxf(mx, v[i]); }
    red[t] = mx; __syncthreads();
    for (int st = 128; st > 0; st >>= 1) { if (t < st) red[t] = fmaxf(red[t], red[t + st]); __syncthreads(); }
    mx = red[0]; __syncthreads();

    float s = 0.f;
#pragma unroll
    for (int i = 0; i < 4; i++) { v[i] = expf(v[i] - mx); s += v[i]; }
    red[t] = s; __syncthreads();
    for (int st = 128; st > 0; st >>= 1) { if (t < st) red[t] += red[t + st]; __syncthreads(); }
    float inv = 1.0f / red[0];

#pragma unroll
    for (int i = 0; i < 4; i++) p[t + i * 256] = v[i] * inv;
}

// ---------------- generic strided transpose: out[c][r] = in[r][c] ----------
__global__ void transpose2(const float* __restrict__ in, int ldin, long long zin,
                           float* __restrict__ out, int ldout, long long zout) {
    __shared__ float t[32][33];
    in  += (long long)blockIdx.z * zin;
    out += (long long)blockIdx.z * zout;
    int r0 = blockIdx.y * 32, c0 = blockIdx.x * 32;
    int x = threadIdx.x, y = threadIdx.y;
#pragma unroll
    for (int i = 0; i < 32; i += 8) t[y + i][x] = in[(size_t)(r0 + y + i) * ldin + c0 + x];
    __syncthreads();
#pragma unroll
    for (int i = 0; i < 32; i += 8) out[(size_t)(c0 + y + i) * ldout + r0 + x] = t[x][y + i];
}

__global__ void prep_bsum(const float* __restrict__ bv) {
    int e = blockIdx.x * 256 + threadIdx.x;
    if (e >= E_) return;
    float s = 0.f;
#pragma unroll
    for (int h = 0; h < H_; h++) s += bv[h * E_ + e];
    g_bsum[e] = s;
}

__global__ void copy_kernel(const float* __restrict__ src, float* __restrict__ dst, int n) {
    int i = blockIdx.x * 256 + threadIdx.x;
    if (i < n) dst[i] = src[i];
}

// ---------------- mma.sync bf16 GEMM, 128x128 tile, BK=16 ------------------
// D = alpha * Aop @ Bop^T  (Aop: [M,K] K-major, Bop: [N,K] K-major)
// 8 warps: 4 (m) x 2 (n); warp tile 32x64 = 2 x 8 fragments of m16n8k16.
// Smem: packed bf16x2, layout [row][kp] with row stride 12 words.
#define SKP 12

template <bool RELU>
__global__ __launch_bounds__(256) void tgemm(
    int K, int zdiv,
    const float* __restrict__ A, int lda, long long sA1, long long sA2,
    const float* __restrict__ Bop, int ldb, long long sB1, long long sB2,
    float* C, int ldc, long long sC1, long long sC2,
    const float* __restrict__ bias,
    const float* __restrict__ res, int ldr, long long sR1, long long sR2,
    float alpha)
{
    __shared__ uint32_t As[2][128][SKP];
    __shared__ uint32_t Bs[2][128][SKP];

    int tid = threadIdx.x;
    int wid = tid >> 5;
    int lane = tid & 31;
    int g = lane >> 2;        // groupID 0..7
    int tig = lane & 3;       // thread-in-group 0..3
    int warp_m = wid & 3;     // 0..3 -> 32-row slab
    int warp_n = wid >> 2;    // 0..1 -> 64-col slab

    int z = blockIdx.z;
    long long zq = z / zdiv, zr = z % zdiv;
    A   += zq * sA1 + zr * sA2;
    Bop += zq * sB1 + zr * sB2;
    C   += zq * sC1 + zr * sC2;
    if (res) res += zq * sR1 + zr * sR2;

    int brow = blockIdx.y * 128;
    int bcol = blockIdx.x * 128;

    // staging: each thread loads 8 consecutive k of one row (2x float4)
    int sr = tid >> 1;            // row 0..127
    int kq = (tid & 1) * 4;       // kp offset 0 or 4 (k offset 0 or 8)

    const float* Ag = A + (size_t)(brow + sr) * lda + kq * 2;
    const float* Bg = Bop + (size_t)(bcol + sr) * ldb + kq * 2;

    float acc[2][8][4];
#pragma unroll
    for (int i = 0; i < 2; i++)
#pragma unroll
        for (int j = 0; j < 8; j++)
#pragma unroll
            for (int c = 0; c < 4; c++) acc[i][j][c] = 0.f;

    int nchunk = K >> 4;

    // prologue: stage chunk 0
    {
        float4 a0 = *reinterpret_cast<const float4*>(Ag);
        float4 a1 = *reinterpret_cast<const float4*>(Ag + 4);
        float4 b0 = *reinterpret_cast<const float4*>(Bg);
        float4 b1 = *reinterpret_cast<const float4*>(Bg + 4);
        As[0][sr][kq + 0] = bf2(a0.x, a0.y); As[0][sr][kq + 1] = bf2(a0.z, a0.w);
        As[0][sr][kq + 2] = bf2(a1.x, a1.y); As[0][sr][kq + 3] = bf2(a1.z, a1.w);
        Bs[0][sr][kq + 0] = bf2(b0.x, b0.y); Bs[0][sr][kq + 1] = bf2(b0.z, b0.w);
        Bs[0][sr][kq + 2] = bf2(b1.x, b1.y); Bs[0][sr][kq + 3] = bf2(b1.z, b1.w);
    }
    __syncthreads();

    int arow0 = warp_m * 32 + g;       // fragment row (mi adds 16)
    int bcol0 = warp_n * 64 + g;       // fragment col (nj adds 8)

    for (int i = 0; i < nchunk; i++) {
        int buf = i & 1;
        float4 pa0, pa1, pb0, pb1;
        if (i + 1 < nchunk) {
            const float* Ap = Ag + (size_t)(i + 1) * 16;
            const float* Bp = Bg + (size_t)(i + 1) * 16;
            pa0 = *reinterpret_cast<const float4*>(Ap);
            pa1 = *reinterpret_cast<const float4*>(Ap + 4);
            pb0 = *reinterpret_cast<const float4*>(Bp);
            pb1 = *reinterpret_cast<const float4*>(Bp + 4);
        }

        uint32_t a[2][4];
#pragma unroll
        for (int mi = 0; mi < 2; mi++) {
            int r0 = arow0 + mi * 16;
            a[mi][0] = As[buf][r0][tig];
            a[mi][1] = As[buf][r0 + 8][tig];
            a[mi][2] = As[buf][r0][tig + 4];
            a[mi][3] = As[buf][r0 + 8][tig + 4];
        }
#pragma unroll
        for (int nj = 0; nj < 8; nj++) {
            int c0 = bcol0 + nj * 8;
            uint32_t b0 = Bs[buf][c0][tig];
            uint32_t b1 = Bs[buf][c0][tig + 4];
#pragma unroll
            for (int mi = 0; mi < 2; mi++)
                mma_bf16(acc[mi][nj][0], acc[mi][nj][1], acc[mi][nj][2], acc[mi][nj][3],
                         a[mi][0], a[mi][1], a[mi][2], a[mi][3], b0, b1);
        }

        if (i + 1 < nchunk) {
            int nb = (i + 1) & 1;
            As[nb][sr][kq + 0] = bf2(pa0.x, pa0.y); As[nb][sr][kq + 1] = bf2(pa0.z, pa0.w);
            As[nb][sr][kq + 2] = bf2(pa1.x, pa1.y); As[nb][sr][kq + 3] = bf2(pa1.z, pa1.w);
            Bs[nb][sr][kq + 0] = bf2(pb0.x, pb0.y); Bs[nb][sr][kq + 1] = bf2(pb0.z, pb0.w);
            Bs[nb][sr][kq + 2] = bf2(pb1.x, pb1.y); Bs[nb][sr][kq + 3] = bf2(pb1.z, pb1.w);
        }
        __syncthreads();
    }

    // epilogue
#pragma unroll
    for (int mi = 0; mi < 2; mi++) {
        int r0 = brow + warp_m * 32 + mi * 16 + g;
#pragma unroll
        for (int nj = 0; nj < 8; nj++) {
            int col = bcol + warp_n * 64 + nj * 8 + 2 * tig;
            float2 bl = bias ? *reinterpret_cast<const float2*>(bias + col)
                             : make_float2(0.f, 0.f);
            float v0 = acc[mi][nj][0] * alpha + bl.x;
            float v1 = acc[mi][nj][1] * alpha + bl.y;
            float v2 = acc[mi][nj][2] * alpha + bl.x;
            float v3 = acc[mi][nj][3] * alpha + bl.y;
            if (res) {
                float2 r0v = *reinterpret_cast<const float2*>(res + (size_t)r0 * ldr + col);
                float2 r1v = *reinterpret_cast<const float2*>(res + (size_t)(r0 + 8) * ldr + col);
                v0 += r0v.x; v1 += r0v.y; v2 += r1v.x; v3 += r1v.y;
            }
            if (RELU) {
                v0 = fmaxf(v0, 0.f); v1 = fmaxf(v1, 0.f);
                v2 = fmaxf(v2, 0.f); v3 = fmaxf(v3, 0.f);
            }
            *reinterpret_cast<float2*>(C + (size_t)r0 * ldc + col) = make_float2(v0, v1);
            *reinterpret_cast<float2*>(C + (size_t)(r0 + 8) * ldc + col) = make_float2(v2, v3);
        }
    }
}

// ---------------- launch ---------------------------------------------------
extern "C" void kernel_launch(void* const* d_in, const int* in_sizes, int n_in,
                              void* d_out, int out_size) {
    const float* x     = (const float*)d_in[0];
    const float* y     = (const float*)d_in[1];
    const float* ln1_g = (const float*)d_in[2];
    const float* ln1_b = (const float*)d_in[3];
    const float* ln2_g = (const float*)d_in[4];
    const float* ln2_b = (const float*)d_in[5];
    const float* ln3_g = (const float*)d_in[6];
    const float* ln3_b = (const float*)d_in[7];
    const float* wq    = (const float*)d_in[8];
    const float* bq    = (const float*)d_in[9];
    const float* wk    = (const float*)d_in[10];
    const float* bk    = (const float*)d_in[11];
    const float* wv    = (const float*)d_in[12];
    const float* bv    = (const float*)d_in[13];
    const float* w_in  = (const float*)d_in[14];
    const float* b_in  = (const float*)d_in[15];
    const float* w_out = (const float*)d_in[16];
    const float* b_out = (const float*)d_in[17];
    float* out = (float*)d_out;

    float *p_xn, *p_yn, *p_ynT, *p_q, *p_k, *p_A, *p_C, *p_w2T;
    float *p_wqT, *p_wkT, *p_winT, *p_woutT, *p_bsum, *p_hn;
    cudaGetSymbolAddress((void**)&p_xn,    g_xn);
    cudaGetSymbolAddress((void**)&p_yn,    g_yn);
    cudaGetSymbolAddress((void**)&p_ynT,   g_ynT);
    cudaGetSymbolAddress((void**)&p_q,     g_q);
    cudaGetSymbolAddress((void**)&p_k,     g_k);
    cudaGetSymbolAddress((void**)&p_A,     g_A);
    cudaGetSymbolAddress((void**)&p_C,     g_C);
    cudaGetSymbolAddress((void**)&p_w2T,   g_w2T);
    cudaGetSymbolAddress((void**)&p_wqT,   g_wqT);
    cudaGetSymbolAddress((void**)&p_wkT,   g_wkT);
    cudaGetSymbolAddress((void**)&p_winT,  g_winT);
    cudaGetSymbolAddress((void**)&p_woutT, g_woutT);
    cudaGetSymbolAddress((void**)&p_bsum,  g_bsum);
    cudaGetSymbolAddress((void**)&p_hn,    g_hn);
    float* p_hpre = p_k;   // reuse after scores GEMM consumed g_k
    float* p_mid  = p_q;   // reuse after scores GEMM consumed g_q

    const int ROWS = B_ * N_TOK;               // 8192
    const size_t CH = (size_t)B_ * N_TOK * E_; // 6291456

    dim3 tb(32, 8);

    // 1. LayerNorms
    ln_kernel<<<ROWS, 256>>>(x, ln1_g, ln1_b, p_xn);
    ln_kernel<<<B_ * M_TOK, 256>>>(y, ln2_g, ln2_b, p_yn);

    // 2. transposes + bias sum
    transpose2<<<dim3(24, 24, 1), tb>>>(wq,    L_,   0, p_wqT,   E_,   0);
    transpose2<<<dim3(24, 24, 1), tb>>>(wk,    L_,   0, p_wkT,   E_,   0);
    transpose2<<<dim3(24, 24, 1), tb>>>(w_in,  L_,   0, p_winT,  E_,   0);
    transpose2<<<dim3(24, 24, 1), tb>>>(w_out, E_,   0, p_woutT, L_,   0);
    transpose2<<<dim3(24, 24, H_), tb>>>(wv, H_ * E_, E_, p_w2T, H_ * E_, E_);
    transpose2<<<dim3(24, 32, B_), tb>>>(p_yn, E_, (long long)M_TOK * E_,
                                          p_ynT, M_TOK, (long long)E_ * M_TOK);
    prep_bsum<<<3, 256>>>(bv);

    // 3. q / k projections
    tgemm<false><<<dim3(6, 64, 1), 256>>>(
        E_, 1, p_xn, E_, 0, 0, p_wqT, E_, 0, 0, p_q, L_, 0, 0,
        bq, nullptr, 0, 0, 0, 1.0f);
    tgemm<false><<<dim3(6, 64, 1), 256>>>(
        E_, 1, p_yn, E_, 0, 0, p_wkT, E_, 0, 0, p_k, L_, 0, 0,
        bk, nullptr, 0, 0, 0, 1.0f);

    // 4. scores: per (b,h) D[1024,1024] = q_h @ k_h^T, alpha = 1/8
    tgemm<false><<<dim3(8, 8, B_ * H_), 256>>>(
        HD_, H_,
        p_q, L_, (long long)N_TOK * L_, HD_,
        p_k, L_, (long long)M_TOK * L_, HD_,
        p_A, M_TOK, (long long)H_ * N_TOK * M_TOK, (long long)N_TOK * M_TOK,
        nullptr, nullptr, 0, 0, 0, 0.125f);

    // 5. softmax
    softmax_kernel<<<B_ * H_ * N_TOK, 256>>>(p_A);

    // 6. C = A_h @ yn  (B operand = ynT[b])
    tgemm<false><<<dim3(6, 8, B_ * H_), 256>>>(
        M_TOK, H_,
        p_A, M_TOK, (long long)H_ * N_TOK * M_TOK, (long long)N_TOK * M_TOK,
        p_ynT, M_TOK, (long long)E_ * M_TOK, 0,
        p_C, H_ * E_, (long long)N_TOK * H_ * E_, E_,
        nullptr, nullptr, 0, 0, 0, 1.0f);

    // 7. h_pre = xn + C @ W2 + bsum
    tgemm<false><<<dim3(6, 64, 1), 256>>>(
        H_ * E_, 1,
        p_C, H_ * E_, 0, 0, p_w2T, H_ * E_, 0, 0, p_hpre, E_, 0, 0,
        p_bsum, p_xn, E_, 0, 0, 1.0f);

    // 8. LN3
    ln_kernel<<<ROWS, 256>>>(p_hpre, ln3_g, ln3_b, p_hn);

    // 9. mid = relu(hn @ w_in + b_in)
    tgemm<true><<<dim3(6, 64, 1), 256>>>(
        E_, 1, p_hn, E_, 0, 0, p_winT, E_, 0, 0, p_mid, L_, 0, 0,
        b_in, nullptr, 0, 0, 0, 1.0f);

    // 10. out = hn + mid @ w_out + b_out
    tgemm<false><<<dim3(6, 64, 1), 256>>>(
        L_, 1, p_mid, L_, 0, 0, p_woutT, L_, 0, 0, out, E_, 0, 0,
        b_out, p_hn, E_, 0, 0, 1.0f);

    // 11. second output: yn
    if ((size_t)out_size >= 2 * CH)
        copy_kernel<<<(int)((CH + 255) / 256), 256>>>(p_yn, out + CH, (int)CH);
}

// round 5
// speedup vs baseline: 4.6129x; 1.1423x over previous
#include <cuda_runtime.h>
#include <cstdint>
#include <cstdio>

typedef unsigned short ushort_t;

// Problem constants
#define B_    8
#define N_TOK 1024
#define M_TOK 1024
#define E_    768
#define L_    768
#define H_    12
#define HD_   64
#define LN_EPS 1e-5f

// ---------------- scratch (static __device__ — no allocations allowed) -----
// bf16 tensors stored as uint32 arrays (pairs) for alignment.
__device__ float    g_xn [B_ * N_TOK * E_];
__device__ float    g_yn [B_ * M_TOK * E_];
__device__ float    g_hn [B_ * N_TOK * E_];
__device__ float    g_A  [(size_t)B_ * H_ * N_TOK * M_TOK];   // fp32 logits (reused: hpre)
__device__ uint32_t g_Ab [(size_t)B_ * H_ * N_TOK * M_TOK / 2]; // bf16 probs
__device__ uint32_t g_qb [B_ * N_TOK * L_ / 2];               // q bf16 (reused: mid)
__device__ uint32_t g_kb [B_ * M_TOK * L_ / 2];               // k bf16
__device__ uint32_t g_Cb [(size_t)B_ * N_TOK * H_ * E_ / 2];  // C bf16
__device__ uint32_t g_ynT[B_ * E_ * M_TOK / 2];               // ynT bf16
__device__ uint32_t g_wqT [L_ * E_ / 2];
__device__ uint32_t g_wkT [L_ * E_ / 2];
__device__ uint32_t g_winT[L_ * E_ / 2];
__device__ uint32_t g_woutT[E_ * L_ / 2];
__device__ uint32_t g_w2T [E_ * H_ * E_ / 2];
__device__ float    g_bsum[E_];

// ---------------- bf16 helpers ---------------------------------------------
__device__ __forceinline__ uint32_t bf2(float lo, float hi) {
    uint32_t r;
    asm("cvt.rn.bf16x2.f32 %0, %1, %2;" : "=r"(r) : "f"(hi), "f"(lo));
    return r;
}
__device__ __forceinline__ ushort_t bf1(float f) {
    ushort_t h; asm("cvt.rn.bf16.f32 %0, %1;" : "=h"(h) : "f"(f)); return h;
}
__device__ __forceinline__ void mma_bf16(float& c0, float& c1, float& c2, float& c3,
                                         uint32_t a0, uint32_t a1, uint32_t a2, uint32_t a3,
                                         uint32_t b0, uint32_t b1) {
    asm volatile(
        "mma.sync.aligned.m16n8k16.row.col.f32.bf16.bf16.f32 "
        "{%0,%1,%2,%3}, {%4,%5,%6,%7}, {%8,%9}, {%0,%1,%2,%3};"
        : "+f"(c0), "+f"(c1), "+f"(c2), "+f"(c3)
        : "r"(a0), "r"(a1), "r"(a2), "r"(a3), "r"(b0), "r"(b1));
}

// ---------------- LayerNorm (optional second destination) ------------------
__global__ void ln_kernel(const float* __restrict__ in, const float* __restrict__ g,
                          const float* __restrict__ b, float* __restrict__ out,
                          float* __restrict__ out2) {
    __shared__ float red[256];
    int row = blockIdx.x;
    int t = threadIdx.x;
    const float* x = in + (size_t)row * E_;
    float* o = out + (size_t)row * E_;

    float v[3];
    float s = 0.f;
#pragma unroll
    for (int i = 0; i < 3; i++) { v[i] = x[t + i * 256]; s += v[i]; }
    red[t] = s; __syncthreads();
    for (int st = 128; st > 0; st >>= 1) { if (t < st) red[t] += red[t + st]; __syncthreads(); }
    float mean = red[0] * (1.0f / E_); __syncthreads();

    float sq = 0.f;
#pragma unroll
    for (int i = 0; i < 3; i++) { float d = v[i] - mean; sq += d * d; }
    red[t] = sq; __syncthreads();
    for (int st = 128; st > 0; st >>= 1) { if (t < st) red[t] += red[t + st]; __syncthreads(); }
    float rstd = rsqrtf(red[0] * (1.0f / E_) + LN_EPS);

#pragma unroll
    for (int i = 0; i < 3; i++) {
        int c = t + i * 256;
        float val = (v[i] - mean) * rstd * g[c] + b[c];
        o[c] = val;
        if (out2) out2[(size_t)row * E_ + c] = val;
    }
}

// ---------------- softmax: fp32 logits in, bf16 probs out ------------------
__global__ void softmax_bf(const float* __restrict__ A, ushort_t* __restrict__ P) {
    __shared__ float red[256];
    size_t row = blockIdx.x;
    int t = threadIdx.x;
    const float4* p4 = reinterpret_cast<const float4*>(A + row * (size_t)M_TOK);

    float4 v = p4[t];
    float mx = fmaxf(fmaxf(v.x, v.y), fmaxf(v.z, v.w));
    red[t] = mx; __syncthreads();
    for (int st = 128; st > 0; st >>= 1) { if (t < st) red[t] = fmaxf(red[t], red[t + st]); __syncthreads(); }
    mx = red[0]; __syncthreads();

    v.x = expf(v.x - mx); v.y = expf(v.y - mx);
    v.z = expf(v.z - mx); v.w = expf(v.w - mx);
    red[t] = v.x + v.y + v.z + v.w; __syncthreads();
    for (int st = 128; st > 0; st >>= 1) { if (t < st) red[t] += red[t + st]; __syncthreads(); }
    float inv = 1.0f / red[0];

    uint2 w = make_uint2(bf2(v.x * inv, v.y * inv), bf2(v.z * inv, v.w * inv));
    reinterpret_cast<uint2*>(P + row * (size_t)M_TOK)[t] = w;
}

// ---------------- strided transpose with bf16 output -----------------------
__global__ void transpose2b(const float* __restrict__ in, int ldin, long long zin,
                            ushort_t* __restrict__ out, int ldout, long long zout) {
    __shared__ float t[32][33];
    in  += (long long)blockIdx.z * zin;
    out += (long long)blockIdx.z * zout;
    int r0 = blockIdx.y * 32, c0 = blockIdx.x * 32;
    int x = threadIdx.x, y = threadIdx.y;
#pragma unroll
    for (int i = 0; i < 32; i += 8) t[y + i][x] = in[(size_t)(r0 + y + i) * ldin + c0 + x];
    __syncthreads();
#pragma unroll
    for (int i = 0; i < 32; i += 8) out[(size_t)(c0 + y + i) * ldout + r0 + x] = bf1(t[x][y + i]);
}

__global__ void prep_bsum(const float* __restrict__ bv) {
    int e = blockIdx.x * 256 + threadIdx.x;
    if (e >= E_) return;
    float s = 0.f;
#pragma unroll
    for (int h = 0; h < H_; h++) s += bv[h * E_ + e];
    g_bsum[e] = s;
}

// ---------------- mma.sync bf16 GEMM, 128x128 tile, BK=16 ------------------
// D = alpha * Aop @ Bop^T  (both operands K-major; bf16 or fp32 sources).
// Smem: interleaved-k pairs so fragment loads are LDS.64.
//   position of k-pair j (0..7): p = 2*(j&3) + (j>>2)
// AT/BT: 0 = fp32 source, 1 = bf16 source.  OT: 0 = fp32 out, 1 = bf16 out.
template <int AT, int BT, int OT, bool RELU>
__global__ __launch_bounds__(256) void tgemm(
    int K, int zdiv,
    const void* __restrict__ Aip, int lda, long long sA1, long long sA2,
    const void* __restrict__ Bip, int ldb, long long sB1, long long sB2,
    void* Cop, int ldc, long long sC1, long long sC2,
    const float* __restrict__ bias,
    const float* __restrict__ res, int ldr, long long sR1, long long sR2,
    float alpha)
{
    __shared__ uint32_t As[2][128][12];
    __shared__ uint32_t Bs[2][128][12];

    int tid = threadIdx.x;
    int wid = tid >> 5;
    int lane = tid & 31;
    int g = lane >> 2;
    int tig = lane & 3;
    int warp_m = wid & 3;
    int warp_n = wid >> 2;

    int z = blockIdx.z;
    long long zq = z / zdiv, zr = z % zdiv;
    long long aoff = zq * sA1 + zr * sA2;
    long long boff = zq * sB1 + zr * sB2;
    long long coff = zq * sC1 + zr * sC2;
    if (res) res += zq * sR1 + zr * sR2;

    int brow = blockIdx.y * 128;
    int bcol = blockIdx.x * 128;

    int sr = tid >> 1;            // staged row 0..127
    int kq = (tid & 1) * 4;       // handles k-pairs kq..kq+3
    int pb = (tid & 1);           // position parity

    // source row pointers
    const float*    Afa = (const float*)Aip + aoff;
    const ushort_t* Aba = (const ushort_t*)Aip + aoff;
    const float*    Bfa = (const float*)Bip + boff;
    const ushort_t* Bba = (const ushort_t*)Bip + boff;

    float acc[2][8][4];
#pragma unroll
    for (int i = 0; i < 2; i++)
#pragma unroll
        for (int j = 0; j < 8; j++)
#pragma unroll
            for (int c = 0; c < 4; c++) acc[i][j][c] = 0.f;

    int nchunk = K >> 4;

    // ---- staging helpers ----
    auto stageA = [&](int buf, float4 v0, float4 v1, uint4 u) {
        uint32_t* d = &As[buf][sr][0];
        if (AT == 0) {
            d[0 + pb] = bf2(v0.x, v0.y); d[2 + pb] = bf2(v0.z, v0.w);
            d[4 + pb] = bf2(v1.x, v1.y); d[6 + pb] = bf2(v1.z, v1.w);
        } else {
            d[0 + pb] = u.x; d[2 + pb] = u.y; d[4 + pb] = u.z; d[6 + pb] = u.w;
        }
    };
    auto stageB = [&](int buf, float4 v0, float4 v1, uint4 u) {
        uint32_t* d = &Bs[buf][sr][0];
        if (BT == 0) {
            d[0 + pb] = bf2(v0.x, v0.y); d[2 + pb] = bf2(v0.z, v0.w);
            d[4 + pb] = bf2(v1.x, v1.y); d[6 + pb] = bf2(v1.z, v1.w);
        } else {
            d[0 + pb] = u.x; d[2 + pb] = u.y; d[4 + pb] = u.z; d[6 + pb] = u.w;
        }
    };
    auto loadA = [&](int k0, float4& v0, float4& v1, uint4& u) {
        if (AT == 0) {
            const float* s = Afa + (size_t)(brow + sr) * lda + k0 + kq * 2;
            v0 = *reinterpret_cast<const float4*>(s);
            v1 = *reinterpret_cast<const float4*>(s + 4);
        } else {
            u = *reinterpret_cast<const uint4*>(Aba + (size_t)(brow + sr) * lda + k0 + kq * 2);
        }
    };
    auto loadB = [&](int k0, float4& v0, float4& v1, uint4& u) {
        if (BT == 0) {
            const float* s = Bfa + (size_t)(bcol + sr) * ldb + k0 + kq * 2;
            v0 = *reinterpret_cast<const float4*>(s);
            v1 = *reinterpret_cast<const float4*>(s + 4);
        } else {
            u = *reinterpret_cast<const uint4*>(Bba + (size_t)(bcol + sr) * ldb + k0 + kq * 2);
        }
    };

    // prologue
    {
        float4 a0, a1, b0, b1; uint4 ua, ub;
        loadA(0, a0, a1, ua); loadB(0, b0, b1, ub);
        stageA(0, a0, a1, ua); stageB(0, b0, b1, ub);
    }
    __syncthreads();

    int arow0 = warp_m * 32 + g;
    int bcol0 = warp_n * 64 + g;

    for (int i = 0; i < nchunk; i++) {
        int buf = i & 1;
        float4 pa0, pa1, pb0, pb1; uint4 pua, pub;
        if (i + 1 < nchunk) {
            loadA((i + 1) * 16, pa0, pa1, pua);
            loadB((i + 1) * 16, pb0, pb1, pub);
        }

        uint32_t a[2][4];
#pragma unroll
        for (int mi = 0; mi < 2; mi++) {
            int r0 = arow0 + mi * 16;
            uint2 lo = *reinterpret_cast<const uint2*>(&As[buf][r0][2 * tig]);
            uint2 hi = *reinterpret_cast<const uint2*>(&As[buf][r0 + 8][2 * tig]);
            a[mi][0] = lo.x; a[mi][1] = hi.x; a[mi][2] = lo.y; a[mi][3] = hi.y;
        }
#pragma unroll
        for (int nj = 0; nj < 8; nj++) {
            int c0 = bcol0 + nj * 8;
            uint2 bb = *reinterpret_cast<const uint2*>(&Bs[buf][c0][2 * tig]);
#pragma unroll
            for (int mi = 0; mi < 2; mi++)
                mma_bf16(acc[mi][nj][0], acc[mi][nj][1], acc[mi][nj][2], acc[mi][nj][3],
                         a[mi][0], a[mi][1], a[mi][2], a[mi][3], bb.x, bb.y);
        }

        if (i + 1 < nchunk) {
            int nb = (i + 1) & 1;
            stageA(nb, pa0, pa1, pua);
            stageB(nb, pb0, pb1, pub);
        }
        __syncthreads();
    }

    // epilogue
    float*    Cf = (float*)Cop + coff;
    ushort_t* Cb = (ushort_t*)Cop + coff;
#pragma unroll
    for (int mi = 0; mi < 2; mi++) {
        int r0 = brow + warp_m * 32 + mi * 16 + g;
#pragma unroll
        for (int nj = 0; nj < 8; nj++) {
            int col = bcol + warp_n * 64 + nj * 8 + 2 * tig;
            float2 bl = bias ? *reinterpret_cast<const float2*>(bias + col)
                             : make_float2(0.f, 0.f);
            float v0 = acc[mi][nj][0] * alpha + bl.x;
            float v1 = acc[mi][nj][1] * alpha + bl.y;
            float v2 = acc[mi][nj][2] * alpha + bl.x;
            float v3 = acc[mi][nj][3] * alpha + bl.y;
            if (res) {
                float2 r0v = *reinterpret_cast<const float2*>(res + (size_t)r0 * ldr + col);
                float2 r1v = *reinterpret_cast<const float2*>(res + (size_t)(r0 + 8) * ldr + col);
                v0 += r0v.x; v1 += r0v.y; v2 += r1v.x; v3 += r1v.y;
            }
            if (RELU) {
                v0 = fmaxf(v0, 0.f); v1 = fmaxf(v1, 0.f);
                v2 = fmaxf(v2, 0.f); v3 = fmaxf(v3, 0.f);
            }
            if (OT == 0) {
                *reinterpret_cast<float2*>(Cf + (size_t)r0 * ldc + col) = make_float2(v0, v1);
                *reinterpret_cast<float2*>(Cf + (size_t)(r0 + 8) * ldc + col) = make_float2(v2, v3);
            } else {
                *reinterpret_cast<uint32_t*>(Cb + (size_t)r0 * ldc + col) = bf2(v0, v1);
                *reinterpret_cast<uint32_t*>(Cb + (size_t)(r0 + 8) * ldc + col) = bf2(v2, v3);
            }
        }
    }
}

// ---------------- launch ---------------------------------------------------
extern "C" void kernel_launch(void* const* d_in, const int* in_sizes, int n_in,
                              void* d_out, int out_size) {
    const float* x     = (const float*)d_in[0];
    const float* y     = (const float*)d_in[1];
    const float* ln1_g = (const float*)d_in[2];
    const float* ln1_b = (const float*)d_in[3];
    const float* ln2_g = (const float*)d_in[4];
    const float* ln2_b = (const float*)d_in[5];
    const float* ln3_g = (const float*)d_in[6];
    const float* ln3_b = (const float*)d_in[7];
    const float* wq    = (const float*)d_in[8];
    const float* bq    = (const float*)d_in[9];
    const float* wk    = (const float*)d_in[10];
    const float* bk    = (const float*)d_in[11];
    const float* wv    = (const float*)d_in[12];
    const float* bv    = (const float*)d_in[13];
    const float* w_in  = (const float*)d_in[14];
    const float* b_in  = (const float*)d_in[15];
    const float* w_out = (const float*)d_in[16];
    const float* b_out = (const float*)d_in[17];
    float* out = (float*)d_out;

    float *p_xn, *p_yn, *p_hn, *p_A, *p_bsum;
    uint32_t *p_Ab, *p_qb, *p_kb, *p_Cb, *p_ynT;
    uint32_t *p_wqT, *p_wkT, *p_winT, *p_woutT, *p_w2T;
    cudaGetSymbolAddress((void**)&p_xn,   g_xn);
    cudaGetSymbolAddress((void**)&p_yn,   g_yn);
    cudaGetSymbolAddress((void**)&p_hn,   g_hn);
    cudaGetSymbolAddress((void**)&p_A,    g_A);
    cudaGetSymbolAddress((void**)&p_Ab,   g_Ab);
    cudaGetSymbolAddress((void**)&p_qb,   g_qb);
    cudaGetSymbolAddress((void**)&p_kb,   g_kb);
    cudaGetSymbolAddress((void**)&p_Cb,   g_Cb);
    cudaGetSymbolAddress((void**)&p_ynT,  g_ynT);
    cudaGetSymbolAddress((void**)&p_wqT,  g_wqT);
    cudaGetSymbolAddress((void**)&p_wkT,  g_wkT);
    cudaGetSymbolAddress((void**)&p_winT, g_winT);
    cudaGetSymbolAddress((void**)&p_woutT,g_woutT);
    cudaGetSymbolAddress((void**)&p_w2T,  g_w2T);
    cudaGetSymbolAddress((void**)&p_bsum, g_bsum);

    float*    p_hpre = p_A;    // reuse logits buffer after softmax consumed it
    uint32_t* p_mid  = p_qb;   // reuse q buffer after scores GEMM consumed it

    const int ROWS = B_ * N_TOK;               // 8192
    const size_t CH = (size_t)B_ * N_TOK * E_; // 6291456
    float* out2 = ((size_t)out_size >= 2 * CH) ? out + CH : nullptr;

    dim3 tb(32, 8);

    // 1. LayerNorms (ln2 dual-writes yn into d_out)
    ln_kernel<<<ROWS, 256>>>(x, ln1_g, ln1_b, p_xn, nullptr);
    ln_kernel<<<B_ * M_TOK, 256>>>(y, ln2_g, ln2_b, p_yn, out2);

    // 2. transposes (bf16 out) + bias sum
    transpose2b<<<dim3(24, 24, 1), tb>>>(wq,    L_, 0, (ushort_t*)p_wqT,   E_, 0);
    transpose2b<<<dim3(24, 24, 1), tb>>>(wk,    L_, 0, (ushort_t*)p_wkT,   E_, 0);
    transpose2b<<<dim3(24, 24, 1), tb>>>(w_in,  L_, 0, (ushort_t*)p_winT,  E_, 0);
    transpose2b<<<dim3(24, 24, 1), tb>>>(w_out, E_, 0, (ushort_t*)p_woutT, L_, 0);
    transpose2b<<<dim3(24, 24, H_), tb>>>(wv, H_ * E_, E_, (ushort_t*)p_w2T, H_ * E_, E_);
    transpose2b<<<dim3(24, 32, B_), tb>>>(p_yn, E_, (long long)M_TOK * E_,
                                           (ushort_t*)p_ynT, M_TOK, (long long)E_ * M_TOK);
    prep_bsum<<<3, 256>>>(bv);

    // 3. q / k projections: fp32 A, bf16 B, bf16 out
    tgemm<0,1,1,false><<<dim3(6, 64, 1), 256>>>(
        E_, 1, p_xn, E_, 0, 0, p_wqT, E_, 0, 0, p_qb, L_, 0, 0,
        bq, nullptr, 0, 0, 0, 1.0f);
    tgemm<0,1,1,false><<<dim3(6, 64, 1), 256>>>(
        E_, 1, p_yn, E_, 0, 0, p_wkT, E_, 0, 0, p_kb, L_, 0, 0,
        bk, nullptr, 0, 0, 0, 1.0f);

    // 4. scores: bf16 q/k, fp32 logits out, alpha = 1/8
    tgemm<1,1,0,false><<<dim3(8, 8, B_ * H_), 256>>>(
        HD_, H_,
        p_qb, L_, (long long)N_TOK * L_, HD_,
        p_kb, L_, (long long)M_TOK * L_, HD_,
        p_A, M_TOK, (long long)H_ * N_TOK * M_TOK, (long long)N_TOK * M_TOK,
        nullptr, nullptr, 0, 0, 0, 0.125f);

    // 5. softmax: fp32 in -> bf16 probs
    softmax_bf<<<B_ * H_ * N_TOK, 256>>>(p_A, (ushort_t*)p_Ab);

    // 6. C = A_h @ yn : bf16 x bf16 -> bf16
    tgemm<1,1,1,false><<<dim3(6, 8, B_ * H_), 256>>>(
        M_TOK, H_,
        p_Ab, M_TOK, (long long)H_ * N_TOK * M_TOK, (long long)N_TOK * M_TOK,
        p_ynT, M_TOK, (long long)E_ * M_TOK, 0,
        p_Cb, H_ * E_, (long long)N_TOK * H_ * E_, E_,
        nullptr, nullptr, 0, 0, 0, 1.0f);

    // 7. h_pre = xn + C @ W2 + bsum : bf16 x bf16 -> fp32
    tgemm<1,1,0,false><<<dim3(6, 64, 1), 256>>>(
        H_ * E_, 1,
        p_Cb, H_ * E_, 0, 0, p_w2T, H_ * E_, 0, 0, p_hpre, E_, 0, 0,
        p_bsum, p_xn, E_, 0, 0, 1.0f);

    // 8. LN3
    ln_kernel<<<ROWS, 256>>>(p_hpre, ln3_g, ln3_b, p_hn, nullptr);

    // 9. mid = relu(hn @ w_in + b_in) : fp32 A -> bf16 out
    tgemm<0,1,1,true><<<dim3(6, 64, 1), 256>>>(
        E_, 1, p_hn, E_, 0, 0, p_winT, E_, 0, 0, p_mid, L_, 0, 0,
        b_in, nullptr, 0, 0, 0, 1.0f);

    // 10. out = hn + mid @ w_out + b_out : bf16 x bf16 -> fp32
    tgemm<1,1,0,false><<<dim3(6, 64, 1), 256>>>(
        L_, 1, p_mid, L_, 0, 0, p_woutT, L_, 0, 0, out, E_, 0, 0,
        b_out, p_hn, E_, 0, 0, 1.0f);
}